// round 1
// baseline (speedup 1.0000x reference)
#include <cuda_runtime.h>

#define NB   16
#define NH   32
#define HD   64
#define TT   8192
#define NX   2048
#define THREADS 256

__global__ __launch_bounds__(THREADS, 4)
void attn_nsm_kernel(const float* __restrict__ q,
                     const float* __restrict__ k,
                     const float* __restrict__ v,
                     const float* __restrict__ past_k,
                     const float* __restrict__ past_v,
                     float* __restrict__ out)
{
    const int bh  = blockIdx.x;        // 0..511  (b*32 + h)
    const int b   = bh >> 5;
    const int h   = bh & 31;
    const int tid = threadIdx.x;

    __shared__ float qs[HD];
    __shared__ float ks[HD];
    __shared__ float w[TT];            // 32 KB
    __shared__ float red[16 * HD];     // 4 KB

    // load q, k for this head into shared
    if (tid < HD) {
        qs[tid] = q[(size_t)b * NX + h * HD + tid];
        ks[tid] = k[(size_t)b * NX + h * HD + tid];
    }
    __syncthreads();

    // ---------------- Phase 1: w[t] = sum_d q[d] * K[d, t] ----------------
    // past_k layout: [B, H, HD, T]  (contiguous in t)
    const float* Kp = past_k + (size_t)bh * HD * TT;

    for (int base = 0; base < TT; base += THREADS * 4) {
        const int t = base + tid * 4;
        float4 acc = make_float4(0.f, 0.f, 0.f, 0.f);
        #pragma unroll 16
        for (int d = 0; d < HD; d++) {
            const float4 kk = *reinterpret_cast<const float4*>(Kp + (size_t)d * TT + t);
            const float qd = qs[d];
            acc.x = fmaf(qd, kk.x, acc.x);
            acc.y = fmaf(qd, kk.y, acc.y);
            acc.z = fmaf(qd, kk.z, acc.z);
            acc.w = fmaf(qd, kk.w, acc.w);
        }
        *reinterpret_cast<float4*>(&w[t]) = acc;
    }
    __syncthreads();

    // ---------------- Phase 2: out[d] = sum_t w[t] * V[t, d] --------------
    // past_v layout: [B, H, T, HD]  (contiguous in d, 256B rows)
    const float* Vp = past_v + (size_t)bh * TT * HD;
    const int dg = tid & 15;       // which float4 along d (0..15)
    const int tg = tid >> 4;       // t-stride group (0..15)

    float4 acc = make_float4(0.f, 0.f, 0.f, 0.f);
    #pragma unroll 8
    for (int t = tg; t < TT; t += 16) {
        const float  wt = w[t];
        const float4 vv = *reinterpret_cast<const float4*>(Vp + (size_t)t * HD + dg * 4);
        acc.x = fmaf(wt, vv.x, acc.x);
        acc.y = fmaf(wt, vv.y, acc.y);
        acc.z = fmaf(wt, vv.z, acc.z);
        acc.w = fmaf(wt, vv.w, acc.w);
    }
    *reinterpret_cast<float4*>(&red[tg * HD + dg * 4]) = acc;
    __syncthreads();

    // ---------------- Reduce + current-token term --------------------------
    if (tid < HD) {
        float s = 0.f;
        #pragma unroll
        for (int g = 0; g < 16; g++) s += red[g * HD + tid];

        // w_cur = q . k  (redundant per thread, 64 FMAs — negligible)
        float wc = 0.f;
        #pragma unroll
        for (int d = 0; d < HD; d++) wc = fmaf(qs[d], ks[d], wc);

        s = fmaf(wc, v[(size_t)b * NX + h * HD + tid], s);
        out[(size_t)b * NX + h * HD + tid] = s;
    }
}

extern "C" void kernel_launch(void* const* d_in, const int* in_sizes, int n_in,
                              void* d_out, int out_size)
{
    const float* q      = (const float*)d_in[0];
    const float* k      = (const float*)d_in[1];
    const float* v      = (const float*)d_in[2];
    const float* past_k = (const float*)d_in[3];
    const float* past_v = (const float*)d_in[4];
    float* out          = (float*)d_out;

    attn_nsm_kernel<<<NB * NH, THREADS>>>(q, k, v, past_k, past_v, out);
}

// round 2
// speedup vs baseline: 1.0714x; 1.0714x over previous
#include <cuda_runtime.h>

#define NB   16
#define NH   32
#define HD   64
#define TT   8192
#define NX   2048
#define TC   1024              // t-chunk per CTA
#define NCHUNK (TT / TC)       // 8
#define THREADS 256

// deterministic scratch: partial[bh][chunk][d]
__device__ float g_partial[NB * NH * NCHUNK * HD];

__global__ __launch_bounds__(THREADS, 4)
void attn_chunk_kernel(const float* __restrict__ q,
                       const float* __restrict__ past_k,
                       const float* __restrict__ past_v)
{
    const int chunk = blockIdx.x;      // 0..7
    const int bh    = blockIdx.y;      // 0..511
    const int b     = bh >> 5;
    const int h     = bh & 31;
    const int tid   = threadIdx.x;

    __shared__ float qs[HD];
    __shared__ float w[TC];            // 4 KB
    __shared__ float red[16 * HD];     // 4 KB

    if (tid < HD)
        qs[tid] = q[(size_t)b * NX + h * HD + tid];
    __syncthreads();

    // ---- Phase A: w[t] = sum_d q[d] * K[d, t] over this chunk ----
    // past_k: [B,H,HD,T], contiguous in t
    const float* Kp = past_k + (size_t)bh * HD * TT + (size_t)chunk * TC;
    {
        const int t = tid * 4;         // 256 threads * 4 = 1024 = TC
        float4 acc = make_float4(0.f, 0.f, 0.f, 0.f);
        #pragma unroll 16
        for (int d = 0; d < HD; d++) {
            const float4 kk = __ldcs(reinterpret_cast<const float4*>(Kp + (size_t)d * TT + t));
            const float qd = qs[d];
            acc.x = fmaf(qd, kk.x, acc.x);
            acc.y = fmaf(qd, kk.y, acc.y);
            acc.z = fmaf(qd, kk.z, acc.z);
            acc.w = fmaf(qd, kk.w, acc.w);
        }
        *reinterpret_cast<float4*>(&w[t]) = acc;
    }
    __syncthreads();

    // ---- Phase B: partial[d] = sum_{t in chunk} w[t] * V[t, d] ----
    // past_v: [B,H,T,HD], contiguous in d (256B rows)
    const float* Vp = past_v + (size_t)bh * TT * HD + (size_t)chunk * TC * HD;
    const int dg = tid & 15;           // float4 index along d
    const int tg = tid >> 4;           // t-stride group

    float4 acc = make_float4(0.f, 0.f, 0.f, 0.f);
    #pragma unroll 8
    for (int t = tg; t < TC; t += 16) {
        const float  wt = w[t];
        const float4 vv = __ldcs(reinterpret_cast<const float4*>(Vp + (size_t)t * HD + dg * 4));
        acc.x = fmaf(wt, vv.x, acc.x);
        acc.y = fmaf(wt, vv.y, acc.y);
        acc.z = fmaf(wt, vv.z, acc.z);
        acc.w = fmaf(wt, vv.w, acc.w);
    }
    *reinterpret_cast<float4*>(&red[tg * HD + dg * 4]) = acc;
    __syncthreads();

    if (tid < HD) {
        float s = 0.f;
        #pragma unroll
        for (int g = 0; g < 16; g++) s += red[g * HD + tid];
        g_partial[((size_t)bh * NCHUNK + chunk) * HD + tid] = s;
    }
}

// ---- Reduce: out[bh][d] = sum_c partial + (q.k) * v[d] ----
__global__ __launch_bounds__(HD)
void attn_reduce_kernel(const float* __restrict__ q,
                        const float* __restrict__ k,
                        const float* __restrict__ v,
                        float* __restrict__ out)
{
    const int bh = blockIdx.x;
    const int b  = bh >> 5;
    const int h  = bh & 31;
    const int d  = threadIdx.x;

    __shared__ float qs[HD];
    __shared__ float ks[HD];
    qs[d] = q[(size_t)b * NX + h * HD + d];
    ks[d] = k[(size_t)b * NX + h * HD + d];
    __syncthreads();

    float s = 0.f;
    #pragma unroll
    for (int c = 0; c < NCHUNK; c++)
        s += g_partial[((size_t)bh * NCHUNK + c) * HD + d];

    float wc = 0.f;
    #pragma unroll
    for (int i = 0; i < HD; i++) wc = fmaf(qs[i], ks[i], wc);

    out[(size_t)b * NX + h * HD + d] = fmaf(wc, v[(size_t)b * NX + h * HD + d], s);
}

extern "C" void kernel_launch(void* const* d_in, const int* in_sizes, int n_in,
                              void* d_out, int out_size)
{
    const float* q      = (const float*)d_in[0];
    const float* k      = (const float*)d_in[1];
    const float* v      = (const float*)d_in[2];
    const float* past_k = (const float*)d_in[3];
    const float* past_v = (const float*)d_in[4];
    float* out          = (float*)d_out;

    dim3 grid(NCHUNK, NB * NH);
    attn_chunk_kernel<<<grid, THREADS>>>(q, past_k, past_v);
    attn_reduce_kernel<<<NB * NH, HD>>>(q, k, v, out);
}